// round 1
// baseline (speedup 1.0000x reference)
#include <cuda_runtime.h>
#include <math.h>

#define BB 8
#define LL 4096
#define DD 256
#define ML (BB*LL)          // 32768 rows total
#define LSPLIT 8            // L-split for kv partials (deterministic reduction)
#define KS_SPLIT 32         // L-split for ksum partials

// ---- scratch (device globals; no allocations allowed) ----
__device__ float g_Q[ML*DD];
__device__ float g_K[ML*DD];
__device__ float g_V[ML*DD];
__device__ float g_kvpart[LSPLIT*BB*DD*DD];   // [b*LSPLIT+s][d][h]
__device__ float g_kv[BB*DD*DD];
__device__ float g_ksum_part[KS_SPLIT*BB*DD];
__device__ float g_ksum[BB*DD];
__device__ float g_z[ML];

// ============================================================
// Input projection GEMM: Y[M,256] = X[M,256] @ W[256,256] + bias
// ACT=1 applies elu(x)+1 (== x+1 for x>0, exp(x) for x<=0)
// Tile: 64x64 output per block, BK=16, 16x16 threads, 4x4 micro-tile
// ============================================================
template<int ACT>
__global__ void gemm_proj(const float* __restrict__ X,
                          const float* __restrict__ W,
                          const float* __restrict__ bias,
                          float* __restrict__ Y)
{
    __shared__ float As[16][64];   // As[k][m]
    __shared__ float Bs[16][64];   // Bs[k][n]

    const int tx = threadIdx.x, ty = threadIdx.y;
    const int tid = ty * 16 + tx;
    const int row0 = blockIdx.y * 64;
    const int col0 = blockIdx.x * 64;

    float acc[4][4] = {};

    for (int k0 = 0; k0 < DD; k0 += 16) {
        #pragma unroll
        for (int i = 0; i < 4; i++) {
            int idx = i * 256 + tid;
            int r = idx >> 4, c = idx & 15;               // A tile 64x16
            As[c][r] = X[(row0 + r) * DD + k0 + c];
            int rb = idx >> 6, cb = idx & 63;             // B tile 16x64
            Bs[rb][cb] = W[(k0 + rb) * DD + col0 + cb];
        }
        __syncthreads();

        #pragma unroll
        for (int kk = 0; kk < 16; kk++) {
            float a[4], b[4];
            #pragma unroll
            for (int i = 0; i < 4; i++) a[i] = As[kk][ty * 4 + i];
            #pragma unroll
            for (int j = 0; j < 4; j++) b[j] = Bs[kk][tx * 4 + j];
            #pragma unroll
            for (int i = 0; i < 4; i++)
                #pragma unroll
                for (int j = 0; j < 4; j++)
                    acc[i][j] = fmaf(a[i], b[j], acc[i][j]);
        }
        __syncthreads();
    }

    #pragma unroll
    for (int i = 0; i < 4; i++) {
        int r = row0 + ty * 4 + i;
        #pragma unroll
        for (int j = 0; j < 4; j++) {
            int c = col0 + tx * 4 + j;
            float v = acc[i][j] + bias[c];
            if (ACT) v = (v > 0.0f) ? (v + 1.0f) : __expf(v);
            Y[r * DD + c] = v;
        }
    }
}

// ============================================================
// kv partials: for batch b, L-slice s:
//   kvpart[b,s][d,h] = sum_{l in slice} K[b,l,d] * V[b,l,h]
// gridDim = (4 hTiles, 4 dTiles, B*LSPLIT)
// ============================================================
__global__ void kv_partial_kernel()
{
    __shared__ float Ks[16][64];   // [l][d]
    __shared__ float Vs[16][64];   // [l][h]

    const int tx = threadIdx.x, ty = threadIdx.y;
    const int tid = ty * 16 + tx;
    const int h0 = blockIdx.x * 64;
    const int d0 = blockIdx.y * 64;
    const int bz = blockIdx.z;               // b*LSPLIT + s
    const int b = bz / LSPLIT;
    const int s = bz % LSPLIT;
    const int lchunk = LL / LSPLIT;          // 512

    const float* Kb = g_K + (size_t)b * LL * DD;
    const float* Vb = g_V + (size_t)b * LL * DD;

    float acc[4][4] = {};

    for (int l0 = s * lchunk; l0 < (s + 1) * lchunk; l0 += 16) {
        #pragma unroll
        for (int i = 0; i < 4; i++) {
            int idx = i * 256 + tid;
            int lr = idx >> 6, cc = idx & 63;
            Ks[lr][cc] = Kb[(l0 + lr) * DD + d0 + cc];
            Vs[lr][cc] = Vb[(l0 + lr) * DD + h0 + cc];
        }
        __syncthreads();

        #pragma unroll
        for (int kk = 0; kk < 16; kk++) {
            float a[4], bv[4];
            #pragma unroll
            for (int i = 0; i < 4; i++) a[i] = Ks[kk][ty * 4 + i];
            #pragma unroll
            for (int j = 0; j < 4; j++) bv[j] = Vs[kk][tx * 4 + j];
            #pragma unroll
            for (int i = 0; i < 4; i++)
                #pragma unroll
                for (int j = 0; j < 4; j++)
                    acc[i][j] = fmaf(a[i], bv[j], acc[i][j]);
        }
        __syncthreads();
    }

    float* out = g_kvpart + (size_t)bz * DD * DD;
    #pragma unroll
    for (int i = 0; i < 4; i++) {
        int d = d0 + ty * 4 + i;
        #pragma unroll
        for (int j = 0; j < 4; j++) {
            int h = h0 + tx * 4 + j;
            out[d * DD + h] = acc[i][j];
        }
    }
}

__global__ void reduce_kv_kernel()
{
    int i = blockIdx.x * blockDim.x + threadIdx.x;    // 0 .. B*D*D-1
    if (i >= BB * DD * DD) return;
    int b = i / (DD * DD);
    int dh = i % (DD * DD);
    float s = 0.0f;
    #pragma unroll
    for (int sp = 0; sp < LSPLIT; sp++)
        s += g_kvpart[(size_t)(b * LSPLIT + sp) * DD * DD + dh];
    g_kv[i] = s;
}

// ksum partials: ksum[b,d] = sum_l K[b,l,d]
__global__ void ksum_partial_kernel()
{
    int s = blockIdx.x;        // 0..KS_SPLIT-1
    int b = blockIdx.y;
    int d = threadIdx.x;       // 0..255
    const int lchunk = LL / KS_SPLIT;   // 128
    const float* Kb = g_K + ((size_t)b * LL + (size_t)s * lchunk) * DD;
    float acc = 0.0f;
    for (int l = 0; l < lchunk; l++) acc += Kb[l * DD + d];
    g_ksum_part[((size_t)s * BB + b) * DD + d] = acc;
}

__global__ void reduce_ksum_kernel()
{
    int i = blockIdx.x * blockDim.x + threadIdx.x;    // 0..B*D-1
    if (i >= BB * DD) return;
    int b = i / DD, d = i % DD;
    float acc = 0.0f;
    #pragma unroll
    for (int s = 0; s < KS_SPLIT; s++)
        acc += g_ksum_part[((size_t)s * BB + b) * DD + d];
    g_ksum[i] = acc;
}

// z[b,l] = dot(Q[b,l,:], ksum[b,:]) + 1e-6   (one warp per row)
__global__ void z_kernel()
{
    int gwarp = (blockIdx.x * blockDim.x + threadIdx.x) >> 5;
    int lane = threadIdx.x & 31;
    if (gwarp >= ML) return;
    int b = gwarp / LL;
    const float* qr = g_Q + (size_t)gwarp * DD;
    const float* ks = g_ksum + (size_t)b * DD;
    float acc = 0.0f;
    #pragma unroll
    for (int c = lane; c < DD; c += 32) acc = fmaf(qr[c], ks[c], acc);
    #pragma unroll
    for (int off = 16; off > 0; off >>= 1)
        acc += __shfl_xor_sync(0xffffffffu, acc, off);
    if (lane == 0) g_z[gwarp] = acc + 1e-6f;
}

// out[row, c] = (Q[row,:] @ kv[b]) [c] / z[row]
__global__ void out_gemm_kernel(float* __restrict__ out)
{
    __shared__ float As[16][64];
    __shared__ float Bs[16][64];

    const int tx = threadIdx.x, ty = threadIdx.y;
    const int tid = ty * 16 + tx;
    const int row0 = blockIdx.y * 64;     // global row (b*L + l)
    const int col0 = blockIdx.x * 64;
    const int b = row0 / LL;              // 64 | 4096, tile stays in one batch

    const float* A = g_Q;
    const float* W = g_kv + (size_t)b * DD * DD;

    float acc[4][4] = {};

    for (int k0 = 0; k0 < DD; k0 += 16) {
        #pragma unroll
        for (int i = 0; i < 4; i++) {
            int idx = i * 256 + tid;
            int r = idx >> 4, c = idx & 15;
            As[c][r] = A[(size_t)(row0 + r) * DD + k0 + c];
            int rb = idx >> 6, cb = idx & 63;
            Bs[rb][cb] = W[(k0 + rb) * DD + col0 + cb];
        }
        __syncthreads();

        #pragma unroll
        for (int kk = 0; kk < 16; kk++) {
            float a[4], bv[4];
            #pragma unroll
            for (int i = 0; i < 4; i++) a[i] = As[kk][ty * 4 + i];
            #pragma unroll
            for (int j = 0; j < 4; j++) bv[j] = Bs[kk][tx * 4 + j];
            #pragma unroll
            for (int i = 0; i < 4; i++)
                #pragma unroll
                for (int j = 0; j < 4; j++)
                    acc[i][j] = fmaf(a[i], bv[j], acc[i][j]);
        }
        __syncthreads();
    }

    #pragma unroll
    for (int i = 0; i < 4; i++) {
        int r = row0 + ty * 4 + i;
        float invz = 1.0f / g_z[r];
        #pragma unroll
        for (int j = 0; j < 4; j++) {
            int c = col0 + tx * 4 + j;
            out[(size_t)r * DD + c] = acc[i][j] * invz;
        }
    }
}

// ============================================================
extern "C" void kernel_launch(void* const* d_in, const int* in_sizes, int n_in,
                              void* d_out, int out_size)
{
    const float* q  = (const float*)d_in[0];
    const float* k  = (const float*)d_in[1];
    const float* v  = (const float*)d_in[2];
    const float* Wq = (const float*)d_in[3];
    const float* bq = (const float*)d_in[4];
    const float* Wk = (const float*)d_in[5];
    const float* bk = (const float*)d_in[6];
    const float* Wv = (const float*)d_in[7];
    const float* bv = (const float*)d_in[8];
    float* out = (float*)d_out;

    float *dQ, *dK, *dV;
    cudaGetSymbolAddress((void**)&dQ, g_Q);
    cudaGetSymbolAddress((void**)&dK, g_K);
    cudaGetSymbolAddress((void**)&dV, g_V);

    dim3 thr(16, 16);

    // 1-3. input projections
    dim3 gProj(DD / 64, ML / 64);
    gemm_proj<1><<<gProj, thr>>>(q, Wq, bq, dQ);
    gemm_proj<1><<<gProj, thr>>>(k, Wk, bk, dK);
    gemm_proj<0><<<gProj, thr>>>(v, Wv, bv, dV);

    // 4. kv = K^T V (partials + deterministic reduce)
    dim3 gKV(DD / 64, DD / 64, BB * LSPLIT);
    kv_partial_kernel<<<gKV, thr>>>();
    reduce_kv_kernel<<<(BB * DD * DD + 255) / 256, 256>>>();

    // 5. ksum
    dim3 gKS(KS_SPLIT, BB);
    ksum_partial_kernel<<<gKS, 256>>>();
    reduce_ksum_kernel<<<(BB * DD + 255) / 256, 256>>>();

    // 6. z
    z_kernel<<<(ML * 32 + 255) / 256, 256>>>();

    // 7. out = Q @ kv / z
    dim3 gOut(DD / 64, ML / 64);
    out_gemm_kernel<<<gOut, thr>>>(out);
}

// round 2
// speedup vs baseline: 1.4447x; 1.4447x over previous
#include <cuda_runtime.h>
#include <math.h>

#define BB 8
#define LL 4096
#define DD 256
#define ML (BB*LL)          // 32768 rows
#define KVS 16              // split-K factor for kv (deterministic)
#define KS_SPLIT 32

// ---- scratch (device globals; no allocations allowed) ----
__device__ float g_Q[ML*DD];
__device__ float g_K[ML*DD];
__device__ float g_V[ML*DD];
__device__ float g_kvpart[KVS*BB*DD*DD];
__device__ float g_kv[BB*DD*DD];
__device__ float g_ksum_part[KS_SPLIT*BB*DD];
__device__ float g_ksum[BB*DD];
__device__ float g_z[ML];

// ============================================================
// Projection GEMM: Y[M,256] = X[M,256] @ W[256,256] + bias, opt elu+1.
// 128x128 tile, BK=8, 256 threads, 8x8 micro-tile, double-buffered smem,
// float4 global loads.
// ============================================================
template<int ACT>
__global__ __launch_bounds__(256)
void gemm_proj(const float* __restrict__ X,
               const float* __restrict__ W,
               const float* __restrict__ bias,
               float* __restrict__ Y)
{
    __shared__ float As[2][8][132];   // [k][m], padded stride
    __shared__ float Bs[2][8][128];   // [k][n]

    const int tid  = threadIdx.x;
    const int row0 = blockIdx.y * 128;
    const int col0 = blockIdx.x * 128;

    // A loader: one float4 per thread. r in 0..127, c4 in {0,4}
    const int ar = tid >> 1;
    const int ac = (tid & 1) * 4;
    // B loader: one float4 per thread. br in 0..7, bc = 4*(tid&31)
    const int br = tid >> 5;
    const int bc = (tid & 31) * 4;

    const float* Aptr = X + (size_t)(row0 + ar) * DD + ac;
    const float* Bptr = W + (size_t)br * DD + col0 + bc;

    const int ty = tid >> 4;   // 0..15
    const int tx = tid & 15;   // 0..15

    float acc[8][8] = {};

    float4 aR = *(const float4*)Aptr;
    float4 bR = *(const float4*)Bptr;
    As[0][ac+0][ar] = aR.x;
    As[0][ac+1][ar] = aR.y;
    As[0][ac+2][ar] = aR.z;
    As[0][ac+3][ar] = aR.w;
    *(float4*)&Bs[0][br][bc] = bR;

    const int NSTAGE = DD / 8;   // 32
    for (int s = 0; s < NSTAGE; s++) {
        __syncthreads();
        if (s + 1 < NSTAGE) {
            aR = *(const float4*)(Aptr + (s + 1) * 8);
            bR = *(const float4*)(Bptr + (size_t)(s + 1) * 8 * DD);
        }
        const int cur = s & 1;
        #pragma unroll
        for (int k = 0; k < 8; k++) {
            float a[8], b[8];
            *(float4*)&a[0] = *(const float4*)&As[cur][k][ty * 8];
            *(float4*)&a[4] = *(const float4*)&As[cur][k][ty * 8 + 4];
            *(float4*)&b[0] = *(const float4*)&Bs[cur][k][tx * 8];
            *(float4*)&b[4] = *(const float4*)&Bs[cur][k][tx * 8 + 4];
            #pragma unroll
            for (int i = 0; i < 8; i++)
                #pragma unroll
                for (int j = 0; j < 8; j++)
                    acc[i][j] = fmaf(a[i], b[j], acc[i][j]);
        }
        if (s + 1 < NSTAGE) {
            const int nxt = cur ^ 1;
            As[nxt][ac+0][ar] = aR.x;
            As[nxt][ac+1][ar] = aR.y;
            As[nxt][ac+2][ar] = aR.z;
            As[nxt][ac+3][ar] = aR.w;
            *(float4*)&Bs[nxt][br][bc] = bR;
        }
    }

    // epilogue
    float bi[8];
    #pragma unroll
    for (int j = 0; j < 8; j++) bi[j] = bias[col0 + tx * 8 + j];
    #pragma unroll
    for (int i = 0; i < 8; i++) {
        const int r = row0 + ty * 8 + i;
        float o[8];
        #pragma unroll
        for (int j = 0; j < 8; j++) {
            float v = acc[i][j] + bi[j];
            if (ACT) v = (v > 0.0f) ? (v + 1.0f) : __expf(v);
            o[j] = v;
        }
        float* dst = Y + (size_t)r * DD + col0 + tx * 8;
        *(float4*)&dst[0] = *(const float4*)&o[0];
        *(float4*)&dst[4] = *(const float4*)&o[4];
    }
}

// ============================================================
// kv split-K partial: kvpart[b,s][d,h] = sum_{l in chunk} K[b,l,d]*V[b,l,h]
// Both operands are [l, feature] row-major -> both load vectorized, no transpose.
// grid = (2 hTiles, 2 dTiles, BB*KVS)
// ============================================================
__global__ __launch_bounds__(256)
void kv_partial_kernel()
{
    __shared__ float As[2][8][128];   // [l][d]
    __shared__ float Bs[2][8][128];   // [l][h]

    const int tid = threadIdx.x;
    const int h0 = blockIdx.x * 128;
    const int d0 = blockIdx.y * 128;
    const int bz = blockIdx.z;
    const int b  = bz / KVS;
    const int sp = bz % KVS;
    const int lchunk = LL / KVS;      // 256
    const int lbase  = sp * lchunk;

    const int lr = tid >> 5;          // 0..7
    const int lc = (tid & 31) * 4;    // 0..124

    const float* Aptr = g_K + ((size_t)b * LL + lbase + lr) * DD + d0 + lc;
    const float* Bptr = g_V + ((size_t)b * LL + lbase + lr) * DD + h0 + lc;

    const int ty = tid >> 4;
    const int tx = tid & 15;

    float acc[8][8] = {};

    float4 aR = *(const float4*)Aptr;
    float4 bR = *(const float4*)Bptr;
    *(float4*)&As[0][lr][lc] = aR;
    *(float4*)&Bs[0][lr][lc] = bR;

    const int NSTAGE = lchunk / 8;    // 32
    for (int s = 0; s < NSTAGE; s++) {
        __syncthreads();
        if (s + 1 < NSTAGE) {
            aR = *(const float4*)(Aptr + (size_t)(s + 1) * 8 * DD);
            bR = *(const float4*)(Bptr + (size_t)(s + 1) * 8 * DD);
        }
        const int cur = s & 1;
        #pragma unroll
        for (int k = 0; k < 8; k++) {
            float a[8], bv[8];
            *(float4*)&a[0]  = *(const float4*)&As[cur][k][ty * 8];
            *(float4*)&a[4]  = *(const float4*)&As[cur][k][ty * 8 + 4];
            *(float4*)&bv[0] = *(const float4*)&Bs[cur][k][tx * 8];
            *(float4*)&bv[4] = *(const float4*)&Bs[cur][k][tx * 8 + 4];
            #pragma unroll
            for (int i = 0; i < 8; i++)
                #pragma unroll
                for (int j = 0; j < 8; j++)
                    acc[i][j] = fmaf(a[i], bv[j], acc[i][j]);
        }
        if (s + 1 < NSTAGE) {
            const int nxt = cur ^ 1;
            *(float4*)&As[nxt][lr][lc] = aR;
            *(float4*)&Bs[nxt][lr][lc] = bR;
        }
    }

    float* out = g_kvpart + (size_t)bz * DD * DD;
    #pragma unroll
    for (int i = 0; i < 8; i++) {
        const int d = d0 + ty * 8 + i;
        float* dst = out + (size_t)d * DD + h0 + tx * 8;
        *(float4*)&dst[0] = *(const float4*)&acc[i][0];
        *(float4*)&dst[4] = *(const float4*)&acc[i][4];
    }
}

__global__ void reduce_kv_kernel()
{
    int i = blockIdx.x * blockDim.x + threadIdx.x;
    if (i >= BB * DD * DD) return;
    int b  = i / (DD * DD);
    int dh = i % (DD * DD);
    float s = 0.0f;
    #pragma unroll
    for (int sp = 0; sp < KVS; sp++)
        s += g_kvpart[(size_t)(b * KVS + sp) * DD * DD + dh];
    g_kv[i] = s;
}

// ksum[b,d] = sum_l K[b,l,d]  (split + deterministic reduce)
__global__ void ksum_partial_kernel()
{
    int s = blockIdx.x, b = blockIdx.y, d = threadIdx.x;
    const int lchunk = LL / KS_SPLIT;
    const float* Kb = g_K + ((size_t)b * LL + (size_t)s * lchunk) * DD;
    float acc = 0.0f;
    for (int l = 0; l < lchunk; l++) acc += Kb[(size_t)l * DD + d];
    g_ksum_part[((size_t)s * BB + b) * DD + d] = acc;
}

__global__ void reduce_ksum_kernel()
{
    int i = blockIdx.x * blockDim.x + threadIdx.x;
    if (i >= BB * DD) return;
    int b = i / DD, d = i % DD;
    float acc = 0.0f;
    #pragma unroll
    for (int s = 0; s < KS_SPLIT; s++)
        acc += g_ksum_part[((size_t)s * BB + b) * DD + d];
    g_ksum[i] = acc;
}

// z[b,l] = dot(Q[b,l,:], ksum[b,:]) + 1e-6  (one warp per row, float4 loads)
__global__ void z_kernel()
{
    int gwarp = (blockIdx.x * blockDim.x + threadIdx.x) >> 5;
    int lane  = threadIdx.x & 31;
    if (gwarp >= ML) return;
    int b = gwarp / LL;
    const float4* qr = (const float4*)(g_Q + (size_t)gwarp * DD);
    const float4* ks = (const float4*)(g_ksum + (size_t)b * DD);
    float acc = 0.0f;
    #pragma unroll
    for (int c = lane; c < DD / 4; c += 32) {
        float4 qv = qr[c], kv4 = ks[c];
        acc = fmaf(qv.x, kv4.x, acc);
        acc = fmaf(qv.y, kv4.y, acc);
        acc = fmaf(qv.z, kv4.z, acc);
        acc = fmaf(qv.w, kv4.w, acc);
    }
    #pragma unroll
    for (int off = 16; off > 0; off >>= 1)
        acc += __shfl_xor_sync(0xffffffffu, acc, off);
    if (lane == 0) g_z[gwarp] = acc + 1e-6f;
}

// out[row,:] = (Q[row,:] @ kv[b]) / z[row]
__global__ __launch_bounds__(256)
void out_gemm_kernel(float* __restrict__ out)
{
    __shared__ float As[2][8][132];
    __shared__ float Bs[2][8][128];

    const int tid  = threadIdx.x;
    const int row0 = blockIdx.y * 128;
    const int col0 = blockIdx.x * 128;
    const int b    = row0 / LL;

    const int ar = tid >> 1;
    const int ac = (tid & 1) * 4;
    const int br = tid >> 5;
    const int bc = (tid & 31) * 4;

    const float* Aptr = g_Q + (size_t)(row0 + ar) * DD + ac;
    const float* Bptr = g_kv + (size_t)b * DD * DD + (size_t)br * DD + col0 + bc;

    const int ty = tid >> 4;
    const int tx = tid & 15;

    float acc[8][8] = {};

    float4 aR = *(const float4*)Aptr;
    float4 bR = *(const float4*)Bptr;
    As[0][ac+0][ar] = aR.x;
    As[0][ac+1][ar] = aR.y;
    As[0][ac+2][ar] = aR.z;
    As[0][ac+3][ar] = aR.w;
    *(float4*)&Bs[0][br][bc] = bR;

    const int NSTAGE = DD / 8;
    for (int s = 0; s < NSTAGE; s++) {
        __syncthreads();
        if (s + 1 < NSTAGE) {
            aR = *(const float4*)(Aptr + (s + 1) * 8);
            bR = *(const float4*)(Bptr + (size_t)(s + 1) * 8 * DD);
        }
        const int cur = s & 1;
        #pragma unroll
        for (int k = 0; k < 8; k++) {
            float a[8], bv[8];
            *(float4*)&a[0]  = *(const float4*)&As[cur][k][ty * 8];
            *(float4*)&a[4]  = *(const float4*)&As[cur][k][ty * 8 + 4];
            *(float4*)&bv[0] = *(const float4*)&Bs[cur][k][tx * 8];
            *(float4*)&bv[4] = *(const float4*)&Bs[cur][k][tx * 8 + 4];
            #pragma unroll
            for (int i = 0; i < 8; i++)
                #pragma unroll
                for (int j = 0; j < 8; j++)
                    acc[i][j] = fmaf(a[i], bv[j], acc[i][j]);
        }
        if (s + 1 < NSTAGE) {
            const int nxt = cur ^ 1;
            As[nxt][ac+0][ar] = aR.x;
            As[nxt][ac+1][ar] = aR.y;
            As[nxt][ac+2][ar] = aR.z;
            As[nxt][ac+3][ar] = aR.w;
            *(float4*)&Bs[nxt][br][bc] = bR;
        }
    }

    #pragma unroll
    for (int i = 0; i < 8; i++) {
        const int r = row0 + ty * 8 + i;
        const float invz = 1.0f / g_z[r];
        float o[8];
        #pragma unroll
        for (int j = 0; j < 8; j++) o[j] = acc[i][j] * invz;
        float* dst = out + (size_t)r * DD + col0 + tx * 8;
        *(float4*)&dst[0] = *(const float4*)&o[0];
        *(float4*)&dst[4] = *(const float4*)&o[4];
    }
}

// ============================================================
extern "C" void kernel_launch(void* const* d_in, const int* in_sizes, int n_in,
                              void* d_out, int out_size)
{
    const float* q  = (const float*)d_in[0];
    const float* k  = (const float*)d_in[1];
    const float* v  = (const float*)d_in[2];
    const float* Wq = (const float*)d_in[3];
    const float* bq = (const float*)d_in[4];
    const float* Wk = (const float*)d_in[5];
    const float* bk = (const float*)d_in[6];
    const float* Wv = (const float*)d_in[7];
    const float* bv = (const float*)d_in[8];
    float* out = (float*)d_out;

    float *dQ, *dK, *dV;
    cudaGetSymbolAddress((void**)&dQ, g_Q);
    cudaGetSymbolAddress((void**)&dK, g_K);
    cudaGetSymbolAddress((void**)&dV, g_V);

    // 1-3. projections: grid (2 colTiles, 256 rowTiles)
    dim3 gProj(DD / 128, ML / 128);
    gemm_proj<1><<<gProj, 256>>>(q, Wq, bq, dQ);
    gemm_proj<1><<<gProj, 256>>>(k, Wk, bk, dK);
    gemm_proj<0><<<gProj, 256>>>(v, Wv, bv, dV);

    // 4. kv = K^T V (split-K partials + deterministic reduce)
    dim3 gKV(DD / 128, DD / 128, BB * KVS);
    kv_partial_kernel<<<gKV, 256>>>();
    reduce_kv_kernel<<<(BB * DD * DD + 255) / 256, 256>>>();

    // 5. ksum
    dim3 gKS(KS_SPLIT, BB);
    ksum_partial_kernel<<<gKS, 256>>>();
    reduce_ksum_kernel<<<(BB * DD + 255) / 256, 256>>>();

    // 6. z
    z_kernel<<<(ML * 32 + 255) / 256, 256>>>();

    // 7. out
    dim3 gOut(DD / 128, ML / 128);
    out_gemm_kernel<<<gOut, 256>>>(out);
}

// round 3
// speedup vs baseline: 2.9751x; 2.0593x over previous
#include <cuda_runtime.h>
#include <math.h>
#include <stdint.h>

#define BB 8
#define LL 4096
#define DD 256
#define ML (BB*LL)          // 32768 rows
#define KVS 8               // split-K for kv (deterministic)
#define KS_SPLIT 32

// ---- scratch (device globals; no allocations allowed) ----
__device__ float g_Q[ML*DD];
__device__ float g_K[ML*DD];
__device__ float g_V[ML*DD];
__device__ float g_kvpart[KVS*BB*DD*DD];
__device__ float g_kv[BB*DD*DD];
__device__ float g_ksum_part[KS_SPLIT*BB*DD];
__device__ float g_ksum[BB*DD];
__device__ float g_z[ML];

// ---- tf32 helpers ----
__device__ __forceinline__ uint32_t f2tf(float x) {
    uint32_t r; asm("cvt.rna.tf32.f32 %0, %1;" : "=r"(r) : "f"(x)); return r;
}
__device__ __forceinline__ void mma8(float* d, const uint32_t* a, const uint32_t* b) {
    asm volatile(
        "mma.sync.aligned.m16n8k8.row.col.f32.tf32.tf32.f32 "
        "{%0,%1,%2,%3}, {%4,%5,%6,%7}, {%8,%9}, {%0,%1,%2,%3};\n"
        : "+f"(d[0]), "+f"(d[1]), "+f"(d[2]), "+f"(d[3])
        : "r"(a[0]), "r"(a[1]), "r"(a[2]), "r"(a[3]), "r"(b[0]), "r"(b[1]));
}

#define SSTR 132   // smem row stride (floats), %4==0 for uint4 stores, breaks bank conflicts

// ============================================================
// Projection: Y[M,256] = act(X[M,256] @ W[256,256] + bias)
// 128x128 tile, BK=16, 8 warps (2m x 4n), warp tile 64x32.
// ============================================================
template<int ACT>
__global__ __launch_bounds__(256)
void proj_mma(const float* __restrict__ X, const float* __restrict__ W,
              const float* __restrict__ bias, float* __restrict__ Y)
{
    __shared__ __align__(16) uint32_t As[2][16][SSTR];  // [k][m]
    __shared__ __align__(16) uint32_t Bs[2][16][SSTR];  // [k][n]

    const int tid  = threadIdx.x;
    const int row0 = blockIdx.y * 128;
    const int col0 = blockIdx.x * 128;

    // A loader: 2 float4/thread: rows tid>>2 and 64+tid>>2, cols (tid&3)*4
    const int ar0 = tid >> 2, ak = (tid & 3) * 4;
    // B loader: 2 float4/thread: rows tid>>5 and 8+tid>>5, cols (tid&31)*4
    const int br0 = tid >> 5, bc = (tid & 31) * 4;

    const int warp = tid >> 5, lane = tid & 31;
    const int wm = warp & 1, wn = warp >> 1;
    const int lr = lane >> 2, lc = lane & 3;

    float acc[4][4][4] = {};

    const float* Ag = X + (size_t)row0 * DD;
    const float* Bg = W + col0;

    float4 aR0, aR1, bR0, bR1;
    aR0 = *(const float4*)(Ag + (size_t)ar0 * DD + ak);
    aR1 = *(const float4*)(Ag + (size_t)(ar0 + 64) * DD + ak);
    bR0 = *(const float4*)(Bg + (size_t)br0 * DD + bc);
    bR1 = *(const float4*)(Bg + (size_t)(br0 + 8) * DD + bc);

    // store stage 0
    {
        As[0][ak+0][ar0] = f2tf(aR0.x); As[0][ak+1][ar0] = f2tf(aR0.y);
        As[0][ak+2][ar0] = f2tf(aR0.z); As[0][ak+3][ar0] = f2tf(aR0.w);
        As[0][ak+0][ar0+64] = f2tf(aR1.x); As[0][ak+1][ar0+64] = f2tf(aR1.y);
        As[0][ak+2][ar0+64] = f2tf(aR1.z); As[0][ak+3][ar0+64] = f2tf(aR1.w);
        uint4 w0 = { f2tf(bR0.x), f2tf(bR0.y), f2tf(bR0.z), f2tf(bR0.w) };
        uint4 w1 = { f2tf(bR1.x), f2tf(bR1.y), f2tf(bR1.z), f2tf(bR1.w) };
        *(uint4*)&Bs[0][br0][bc]   = w0;
        *(uint4*)&Bs[0][br0+8][bc] = w1;
    }

    const int NST = DD / 16;   // 16
    for (int s = 0; s < NST; s++) {
        __syncthreads();
        if (s + 1 < NST) {
            const int k0 = (s + 1) * 16;
            aR0 = *(const float4*)(Ag + (size_t)ar0 * DD + k0 + ak);
            aR1 = *(const float4*)(Ag + (size_t)(ar0 + 64) * DD + k0 + ak);
            bR0 = *(const float4*)(Bg + (size_t)(k0 + br0) * DD + bc);
            bR1 = *(const float4*)(Bg + (size_t)(k0 + br0 + 8) * DD + bc);
        }
        const int cur = s & 1;
        #pragma unroll
        for (int ks = 0; ks < 2; ks++) {
            const int kb = ks * 8;
            uint32_t af[4][4], bf[4][2];
            #pragma unroll
            for (int mt = 0; mt < 4; mt++) {
                const int m = wm * 64 + mt * 16 + lr;
                af[mt][0] = As[cur][kb+lc][m];
                af[mt][1] = As[cur][kb+lc][m+8];
                af[mt][2] = As[cur][kb+4+lc][m];
                af[mt][3] = As[cur][kb+4+lc][m+8];
            }
            #pragma unroll
            for (int nt = 0; nt < 4; nt++) {
                const int n = wn * 32 + nt * 8 + lr;
                bf[nt][0] = Bs[cur][kb+lc][n];
                bf[nt][1] = Bs[cur][kb+4+lc][n];
            }
            #pragma unroll
            for (int mt = 0; mt < 4; mt++)
                #pragma unroll
                for (int nt = 0; nt < 4; nt++)
                    mma8(acc[mt][nt], af[mt], bf[nt]);
        }
        if (s + 1 < NST) {
            const int nxt = cur ^ 1;
            As[nxt][ak+0][ar0] = f2tf(aR0.x); As[nxt][ak+1][ar0] = f2tf(aR0.y);
            As[nxt][ak+2][ar0] = f2tf(aR0.z); As[nxt][ak+3][ar0] = f2tf(aR0.w);
            As[nxt][ak+0][ar0+64] = f2tf(aR1.x); As[nxt][ak+1][ar0+64] = f2tf(aR1.y);
            As[nxt][ak+2][ar0+64] = f2tf(aR1.z); As[nxt][ak+3][ar0+64] = f2tf(aR1.w);
            uint4 w0 = { f2tf(bR0.x), f2tf(bR0.y), f2tf(bR0.z), f2tf(bR0.w) };
            uint4 w1 = { f2tf(bR1.x), f2tf(bR1.y), f2tf(bR1.z), f2tf(bR1.w) };
            *(uint4*)&Bs[nxt][br0][bc]   = w0;
            *(uint4*)&Bs[nxt][br0+8][bc] = w1;
        }
    }

    // epilogue
    #pragma unroll
    for (int mt = 0; mt < 4; mt++) {
        const int r0 = row0 + wm * 64 + mt * 16 + lr;
        #pragma unroll
        for (int nt = 0; nt < 4; nt++) {
            const int c = col0 + wn * 32 + nt * 8 + 2 * lc;
            const float b0 = bias[c], b1 = bias[c+1];
            float v0 = acc[mt][nt][0] + b0;
            float v1 = acc[mt][nt][1] + b1;
            float v2 = acc[mt][nt][2] + b0;
            float v3 = acc[mt][nt][3] + b1;
            if (ACT) {
                v0 = (v0 > 0.0f) ? (v0 + 1.0f) : __expf(v0);
                v1 = (v1 > 0.0f) ? (v1 + 1.0f) : __expf(v1);
                v2 = (v2 > 0.0f) ? (v2 + 1.0f) : __expf(v2);
                v3 = (v3 > 0.0f) ? (v3 + 1.0f) : __expf(v3);
            }
            float2 p0 = { v0, v1 }, p1 = { v2, v3 };
            *(float2*)&Y[(size_t)r0 * DD + c]       = p0;
            *(float2*)&Y[(size_t)(r0+8) * DD + c]   = p1;
        }
    }
}

// ============================================================
// kv split-K: kvpart[bz][d,h] = sum_{l in chunk} K[b,l,d]*V[b,l,h]
// A tile = K[l, d] already in [k][m] layout; B tile = V[l, h] = [k][n].
// grid = (2 hTiles, 2 dTiles, BB*KVS)
// ============================================================
__global__ __launch_bounds__(256)
void kv_mma()
{
    __shared__ __align__(16) uint32_t As[2][16][SSTR];  // [l][d]
    __shared__ __align__(16) uint32_t Bs[2][16][SSTR];  // [l][h]

    const int tid = threadIdx.x;
    const int h0 = blockIdx.x * 128;
    const int d0 = blockIdx.y * 128;
    const int bz = blockIdx.z;
    const int b  = bz / KVS;
    const int sp = bz % KVS;
    const int lchunk = LL / KVS;      // 512
    const size_t base = ((size_t)b * LL + (size_t)sp * lchunk) * DD;

    // loader: 2 float4/thread per operand: rows tid>>5 and 8+tid>>5, cols (tid&31)*4
    const int kr0 = tid >> 5, mc = (tid & 31) * 4;

    const int warp = tid >> 5, lane = tid & 31;
    const int wm = warp & 1, wn = warp >> 1;
    const int lr = lane >> 2, lc = lane & 3;

    float acc[4][4][4] = {};

    const float* Ag = g_K + base + d0;
    const float* Bg = g_V + base + h0;

    float4 aR0, aR1, bR0, bR1;
    aR0 = *(const float4*)(Ag + (size_t)kr0 * DD + mc);
    aR1 = *(const float4*)(Ag + (size_t)(kr0 + 8) * DD + mc);
    bR0 = *(const float4*)(Bg + (size_t)kr0 * DD + mc);
    bR1 = *(const float4*)(Bg + (size_t)(kr0 + 8) * DD + mc);
    {
        uint4 a0 = { f2tf(aR0.x), f2tf(aR0.y), f2tf(aR0.z), f2tf(aR0.w) };
        uint4 a1 = { f2tf(aR1.x), f2tf(aR1.y), f2tf(aR1.z), f2tf(aR1.w) };
        uint4 b0 = { f2tf(bR0.x), f2tf(bR0.y), f2tf(bR0.z), f2tf(bR0.w) };
        uint4 b1 = { f2tf(bR1.x), f2tf(bR1.y), f2tf(bR1.z), f2tf(bR1.w) };
        *(uint4*)&As[0][kr0][mc]   = a0;
        *(uint4*)&As[0][kr0+8][mc] = a1;
        *(uint4*)&Bs[0][kr0][mc]   = b0;
        *(uint4*)&Bs[0][kr0+8][mc] = b1;
    }

    const int NST = lchunk / 16;   // 32
    for (int s = 0; s < NST; s++) {
        __syncthreads();
        if (s + 1 < NST) {
            const size_t l0 = (size_t)(s + 1) * 16;
            aR0 = *(const float4*)(Ag + (l0 + kr0) * DD + mc);
            aR1 = *(const float4*)(Ag + (l0 + kr0 + 8) * DD + mc);
            bR0 = *(const float4*)(Bg + (l0 + kr0) * DD + mc);
            bR1 = *(const float4*)(Bg + (l0 + kr0 + 8) * DD + mc);
        }
        const int cur = s & 1;
        #pragma unroll
        for (int ks = 0; ks < 2; ks++) {
            const int kb = ks * 8;
            uint32_t af[4][4], bf[4][2];
            #pragma unroll
            for (int mt = 0; mt < 4; mt++) {
                const int m = wm * 64 + mt * 16 + lr;
                af[mt][0] = As[cur][kb+lc][m];
                af[mt][1] = As[cur][kb+lc][m+8];
                af[mt][2] = As[cur][kb+4+lc][m];
                af[mt][3] = As[cur][kb+4+lc][m+8];
            }
            #pragma unroll
            for (int nt = 0; nt < 4; nt++) {
                const int n = wn * 32 + nt * 8 + lr;
                bf[nt][0] = Bs[cur][kb+lc][n];
                bf[nt][1] = Bs[cur][kb+4+lc][n];
            }
            #pragma unroll
            for (int mt = 0; mt < 4; mt++)
                #pragma unroll
                for (int nt = 0; nt < 4; nt++)
                    mma8(acc[mt][nt], af[mt], bf[nt]);
        }
        if (s + 1 < NST) {
            const int nxt = cur ^ 1;
            uint4 a0 = { f2tf(aR0.x), f2tf(aR0.y), f2tf(aR0.z), f2tf(aR0.w) };
            uint4 a1 = { f2tf(aR1.x), f2tf(aR1.y), f2tf(aR1.z), f2tf(aR1.w) };
            uint4 b0 = { f2tf(bR0.x), f2tf(bR0.y), f2tf(bR0.z), f2tf(bR0.w) };
            uint4 b1 = { f2tf(bR1.x), f2tf(bR1.y), f2tf(bR1.z), f2tf(bR1.w) };
            *(uint4*)&As[nxt][kr0][mc]   = a0;
            *(uint4*)&As[nxt][kr0+8][mc] = a1;
            *(uint4*)&Bs[nxt][kr0][mc]   = b0;
            *(uint4*)&Bs[nxt][kr0+8][mc] = b1;
        }
    }

    float* outp = g_kvpart + (size_t)bz * DD * DD;
    #pragma unroll
    for (int mt = 0; mt < 4; mt++) {
        const int d = d0 + wm * 64 + mt * 16 + lr;
        #pragma unroll
        for (int nt = 0; nt < 4; nt++) {
            const int h = h0 + wn * 32 + nt * 8 + 2 * lc;
            float2 p0 = { acc[mt][nt][0], acc[mt][nt][1] };
            float2 p1 = { acc[mt][nt][2], acc[mt][nt][3] };
            *(float2*)&outp[(size_t)d * DD + h]     = p0;
            *(float2*)&outp[(size_t)(d+8) * DD + h] = p1;
        }
    }
}

__global__ void reduce_kv_kernel()
{
    int i = blockIdx.x * blockDim.x + threadIdx.x;
    if (i >= BB * DD * DD) return;
    int b  = i / (DD * DD);
    int dh = i % (DD * DD);
    float s = 0.0f;
    #pragma unroll
    for (int sp = 0; sp < KVS; sp++)
        s += g_kvpart[(size_t)(b * KVS + sp) * DD * DD + dh];
    g_kv[i] = s;
}

// ksum[b,d] = sum_l K[b,l,d]  (fp32, split + deterministic reduce)
__global__ void ksum_partial_kernel()
{
    int s = blockIdx.x, b = blockIdx.y, d = threadIdx.x;
    const int lchunk = LL / KS_SPLIT;
    const float* Kb = g_K + ((size_t)b * LL + (size_t)s * lchunk) * DD;
    float acc = 0.0f;
    for (int l = 0; l < lchunk; l++) acc += Kb[(size_t)l * DD + d];
    g_ksum_part[((size_t)s * BB + b) * DD + d] = acc;
}

__global__ void reduce_ksum_kernel()
{
    int i = blockIdx.x * blockDim.x + threadIdx.x;
    if (i >= BB * DD) return;
    int b = i / DD, d = i % DD;
    float acc = 0.0f;
    #pragma unroll
    for (int s = 0; s < KS_SPLIT; s++)
        acc += g_ksum_part[((size_t)s * BB + b) * DD + d];
    g_ksum[i] = acc;
}

// z[b,l] = dot(Q[b,l,:], ksum[b,:]) + 1e-6  (fp32, one warp per row)
__global__ void z_kernel()
{
    int gwarp = (blockIdx.x * blockDim.x + threadIdx.x) >> 5;
    int lane  = threadIdx.x & 31;
    if (gwarp >= ML) return;
    int b = gwarp / LL;
    const float4* qr = (const float4*)(g_Q + (size_t)gwarp * DD);
    const float4* ks = (const float4*)(g_ksum + (size_t)b * DD);
    float acc = 0.0f;
    #pragma unroll
    for (int c = lane; c < DD / 4; c += 32) {
        float4 qv = qr[c], kv4 = ks[c];
        acc = fmaf(qv.x, kv4.x, acc);
        acc = fmaf(qv.y, kv4.y, acc);
        acc = fmaf(qv.z, kv4.z, acc);
        acc = fmaf(qv.w, kv4.w, acc);
    }
    #pragma unroll
    for (int off = 16; off > 0; off >>= 1)
        acc += __shfl_xor_sync(0xffffffffu, acc, off);
    if (lane == 0) g_z[gwarp] = acc + 1e-6f;
}

// ============================================================
// out[row,:] = (Q[row,:] @ kv[b]) / z[row]
// ============================================================
__global__ __launch_bounds__(256)
void out_mma(float* __restrict__ out)
{
    __shared__ __align__(16) uint32_t As[2][16][SSTR];
    __shared__ __align__(16) uint32_t Bs[2][16][SSTR];

    const int tid  = threadIdx.x;
    const int row0 = blockIdx.y * 128;
    const int col0 = blockIdx.x * 128;
    const int b    = row0 / LL;

    const int ar0 = tid >> 2, ak = (tid & 3) * 4;
    const int br0 = tid >> 5, bc = (tid & 31) * 4;

    const int warp = tid >> 5, lane = tid & 31;
    const int wm = warp & 1, wn = warp >> 1;
    const int lr = lane >> 2, lc = lane & 3;

    float acc[4][4][4] = {};

    const float* Ag = g_Q + (size_t)row0 * DD;
    const float* Bg = g_kv + (size_t)b * DD * DD + col0;

    float4 aR0, aR1, bR0, bR1;
    aR0 = *(const float4*)(Ag + (size_t)ar0 * DD + ak);
    aR1 = *(const float4*)(Ag + (size_t)(ar0 + 64) * DD + ak);
    bR0 = *(const float4*)(Bg + (size_t)br0 * DD + bc);
    bR1 = *(const float4*)(Bg + (size_t)(br0 + 8) * DD + bc);
    {
        As[0][ak+0][ar0] = f2tf(aR0.x); As[0][ak+1][ar0] = f2tf(aR0.y);
        As[0][ak+2][ar0] = f2tf(aR0.z); As[0][ak+3][ar0] = f2tf(aR0.w);
        As[0][ak+0][ar0+64] = f2tf(aR1.x); As[0][ak+1][ar0+64] = f2tf(aR1.y);
        As[0][ak+2][ar0+64] = f2tf(aR1.z); As[0][ak+3][ar0+64] = f2tf(aR1.w);
        uint4 w0 = { f2tf(bR0.x), f2tf(bR0.y), f2tf(bR0.z), f2tf(bR0.w) };
        uint4 w1 = { f2tf(bR1.x), f2tf(bR1.y), f2tf(bR1.z), f2tf(bR1.w) };
        *(uint4*)&Bs[0][br0][bc]   = w0;
        *(uint4*)&Bs[0][br0+8][bc] = w1;
    }

    const int NST = DD / 16;
    for (int s = 0; s < NST; s++) {
        __syncthreads();
        if (s + 1 < NST) {
            const int k0 = (s + 1) * 16;
            aR0 = *(const float4*)(Ag + (size_t)ar0 * DD + k0 + ak);
            aR1 = *(const float4*)(Ag + (size_t)(ar0 + 64) * DD + k0 + ak);
            bR0 = *(const float4*)(Bg + (size_t)(k0 + br0) * DD + bc);
            bR1 = *(const float4*)(Bg + (size_t)(k0 + br0 + 8) * DD + bc);
        }
        const int cur = s & 1;
        #pragma unroll
        for (int ks = 0; ks < 2; ks++) {
            const int kb = ks * 8;
            uint32_t af[4][4], bf[4][2];
            #pragma unroll
            for (int mt = 0; mt < 4; mt++) {
                const int m = wm * 64 + mt * 16 + lr;
                af[mt][0] = As[cur][kb+lc][m];
                af[mt][1] = As[cur][kb+lc][m+8];
                af[mt][2] = As[cur][kb+4+lc][m];
                af[mt][3] = As[cur][kb+4+lc][m+8];
            }
            #pragma unroll
            for (int nt = 0; nt < 4; nt++) {
                const int n = wn * 32 + nt * 8 + lr;
                bf[nt][0] = Bs[cur][kb+lc][n];
                bf[nt][1] = Bs[cur][kb+4+lc][n];
            }
            #pragma unroll
            for (int mt = 0; mt < 4; mt++)
                #pragma unroll
                for (int nt = 0; nt < 4; nt++)
                    mma8(acc[mt][nt], af[mt], bf[nt]);
        }
        if (s + 1 < NST) {
            const int nxt = cur ^ 1;
            As[nxt][ak+0][ar0] = f2tf(aR0.x); As[nxt][ak+1][ar0] = f2tf(aR0.y);
            As[nxt][ak+2][ar0] = f2tf(aR0.z); As[nxt][ak+3][ar0] = f2tf(aR0.w);
            As[nxt][ak+0][ar0+64] = f2tf(aR1.x); As[nxt][ak+1][ar0+64] = f2tf(aR1.y);
            As[nxt][ak+2][ar0+64] = f2tf(aR1.z); As[nxt][ak+3][ar0+64] = f2tf(aR1.w);
            uint4 w0 = { f2tf(bR0.x), f2tf(bR0.y), f2tf(bR0.z), f2tf(bR0.w) };
            uint4 w1 = { f2tf(bR1.x), f2tf(bR1.y), f2tf(bR1.z), f2tf(bR1.w) };
            *(uint4*)&Bs[nxt][br0][bc]   = w0;
            *(uint4*)&Bs[nxt][br0+8][bc] = w1;
        }
    }

    #pragma unroll
    for (int mt = 0; mt < 4; mt++) {
        const int r0 = row0 + wm * 64 + mt * 16 + lr;
        const float iz0 = 1.0f / g_z[r0];
        const float iz1 = 1.0f / g_z[r0 + 8];
        #pragma unroll
        for (int nt = 0; nt < 4; nt++) {
            const int c = col0 + wn * 32 + nt * 8 + 2 * lc;
            float2 p0 = { acc[mt][nt][0] * iz0, acc[mt][nt][1] * iz0 };
            float2 p1 = { acc[mt][nt][2] * iz1, acc[mt][nt][3] * iz1 };
            *(float2*)&out[(size_t)r0 * DD + c]       = p0;
            *(float2*)&out[(size_t)(r0+8) * DD + c]   = p1;
        }
    }
}

// ============================================================
extern "C" void kernel_launch(void* const* d_in, const int* in_sizes, int n_in,
                              void* d_out, int out_size)
{
    const float* q  = (const float*)d_in[0];
    const float* k  = (const float*)d_in[1];
    const float* v  = (const float*)d_in[2];
    const float* Wq = (const float*)d_in[3];
    const float* bq = (const float*)d_in[4];
    const float* Wk = (const float*)d_in[5];
    const float* bk = (const float*)d_in[6];
    const float* Wv = (const float*)d_in[7];
    const float* bv = (const float*)d_in[8];
    float* out = (float*)d_out;

    float *dQ, *dK, *dV;
    cudaGetSymbolAddress((void**)&dQ, g_Q);
    cudaGetSymbolAddress((void**)&dK, g_K);
    cudaGetSymbolAddress((void**)&dV, g_V);

    // 1-3. projections (tensor cores)
    dim3 gProj(DD / 128, ML / 128);
    proj_mma<1><<<gProj, 256>>>(q, Wq, bq, dQ);
    proj_mma<1><<<gProj, 256>>>(k, Wk, bk, dK);
    proj_mma<0><<<gProj, 256>>>(v, Wv, bv, dV);

    // 4. kv = K^T V (tensor cores, split-K + deterministic reduce)
    dim3 gKV(DD / 128, DD / 128, BB * KVS);
    kv_mma<<<gKV, 256>>>();
    reduce_kv_kernel<<<(BB * DD * DD + 255) / 256, 256>>>();

    // 5. ksum (fp32)
    dim3 gKS(KS_SPLIT, BB);
    ksum_partial_kernel<<<gKS, 256>>>();
    reduce_ksum_kernel<<<(BB * DD + 255) / 256, 256>>>();

    // 6. z (fp32)
    z_kernel<<<(ML * 32 + 255) / 256, 256>>>();

    // 7. out (tensor cores)
    dim3 gOut(DD / 128, ML / 128);
    out_mma<<<gOut, 256>>>(out);
}

// round 4
// speedup vs baseline: 3.2839x; 1.1038x over previous
#include <cuda_runtime.h>
#include <math.h>
#include <stdint.h>

#define BB 8
#define LL 4096
#define DD 256
#define ML (BB*LL)          // 32768 rows
#define KVS 8               // split-K for kv (deterministic)
#define KS_SPLIT 32

#define AP 20    // proj/out A smem row stride (16 k + 4 pad floats)
#define BP 132   // [k][n] smem row stride

// ---- scratch (device globals; no allocations allowed) ----
__device__ float g_Q[ML*DD];
__device__ float g_K[ML*DD];
__device__ float g_V[ML*DD];
__device__ float g_kvpart[KVS*BB*DD*DD];
__device__ float g_kv[BB*DD*DD];
__device__ float g_ksum_part[KS_SPLIT*BB*DD];
__device__ float g_ksum[BB*DD];
__device__ float g_z[ML];

// ---- helpers ----
__device__ __forceinline__ uint32_t f2tf(float x) {
    uint32_t r; asm("cvt.rna.tf32.f32 %0, %1;" : "=r"(r) : "f"(x)); return r;
}
__device__ __forceinline__ void mma8(float* d, const uint32_t* a, const uint32_t* b) {
    asm volatile(
        "mma.sync.aligned.m16n8k8.row.col.f32.tf32.tf32.f32 "
        "{%0,%1,%2,%3}, {%4,%5,%6,%7}, {%8,%9}, {%0,%1,%2,%3};\n"
        : "+f"(d[0]), "+f"(d[1]), "+f"(d[2]), "+f"(d[3])
        : "r"(a[0]), "r"(a[1]), "r"(a[2]), "r"(a[3]), "r"(b[0]), "r"(b[1]));
}
__device__ __forceinline__ void cp16(uint32_t saddr, const void* g) {
    asm volatile("cp.async.cg.shared.global [%0], [%1], 16;\n"
                 :: "r"(saddr), "l"(g) : "memory");
}
#define CP_COMMIT() asm volatile("cp.async.commit_group;\n" ::: "memory")
#define CP_WAIT1()  asm volatile("cp.async.wait_group 1;\n" ::: "memory")
#define CP_WAIT0()  asm volatile("cp.async.wait_group 0;\n" ::: "memory")

// fragment MMA sweep: af[4][4], bf[4][2] -> acc[4][4][4]
__device__ __forceinline__ void mma_sweep(float acc[4][4][4],
                                          const uint32_t af[4][4],
                                          const uint32_t bf[4][2]) {
    #pragma unroll
    for (int mt = 0; mt < 4; mt++)
        #pragma unroll
        for (int nt = 0; nt < 4; nt++)
            mma8(acc[mt][nt], af[mt], bf[nt]);
}

// ============================================================
// Projection: Y = act(X @ W + bias). 128x128 tile, BK=16,
// cp.async 2-stage, fragment double-buffer, tf32 mma.
// ============================================================
template<int ACT>
__global__ __launch_bounds__(256)
void proj_mma(const float* __restrict__ X, const float* __restrict__ W,
              const float* __restrict__ bias, float* __restrict__ Y)
{
    __shared__ __align__(16) float As[2][128*AP];   // [m][k]
    __shared__ __align__(16) float Bs[2][16*BP];    // [k][n]

    const int tid  = threadIdx.x;
    const int row0 = blockIdx.y * 128;
    const int col0 = blockIdx.x * 128;

    const int warp = tid >> 5, lane = tid & 31;
    const int wm = warp & 1, wn = warp >> 1;
    const int lr = lane >> 2, lc = lane & 3;

    // A loader: chunks c = 2*tid+{0,1}; row=c>>2 (0..127), off=(c&3)*4
    const int a_r   = (2 * tid) >> 2;
    const int a_off = ((2 * tid) & 3) * 4;
    // B loader: row=c>>5 (0..15), off=(c&31)*4
    const int b_r   = (2 * tid) >> 5;
    const int b_off = ((2 * tid) & 31) * 4;

    const float* Ag = X + (size_t)(row0 + a_r) * DD + a_off;
    const float* Bg = W + (size_t)b_r * DD + col0 + b_off;

    const uint32_t sA0 = (uint32_t)__cvta_generic_to_shared(&As[0][0]);
    const uint32_t sB0 = (uint32_t)__cvta_generic_to_shared(&Bs[0][0]);

    float acc[4][4][4] = {};

    #define PROJ_ISSUE(st, k0) do {                                           \
        cp16(sA0 + ((st)*128*AP + a_r*AP + a_off) * 4,      Ag + (k0));        \
        cp16(sA0 + ((st)*128*AP + a_r*AP + a_off + 4) * 4,  Ag + (k0) + 4);    \
        cp16(sB0 + ((st)*16*BP + b_r*BP + b_off) * 4,       Bg + (size_t)(k0)*DD);     \
        cp16(sB0 + ((st)*16*BP + b_r*BP + b_off + 4) * 4,   Bg + (size_t)(k0)*DD + 4); \
    } while (0)

    #define PROJ_LDFRAG(af, bf, st, kb) do {                                   \
        _Pragma("unroll")                                                      \
        for (int mt = 0; mt < 4; mt++) {                                       \
            const int m = wm * 64 + mt * 16 + lr;                              \
            af[mt][0] = f2tf(As[st][(m)   * AP + (kb) + lc]);                  \
            af[mt][1] = f2tf(As[st][(m+8) * AP + (kb) + lc]);                  \
            af[mt][2] = f2tf(As[st][(m)   * AP + (kb) + lc + 4]);              \
            af[mt][3] = f2tf(As[st][(m+8) * AP + (kb) + lc + 4]);              \
        }                                                                      \
        _Pragma("unroll")                                                      \
        for (int nt = 0; nt < 4; nt++) {                                       \
            const int n = wn * 32 + nt * 8 + lr;                               \
            bf[nt][0] = f2tf(Bs[st][((kb) + lc)     * BP + n]);                \
            bf[nt][1] = f2tf(Bs[st][((kb) + 4 + lc) * BP + n]);                \
        }                                                                      \
    } while (0)

    PROJ_ISSUE(0, 0);  CP_COMMIT();
    PROJ_ISSUE(1, 16); CP_COMMIT();
    CP_WAIT1();
    __syncthreads();

    uint32_t af0[4][4], bf0[4][2], af1[4][4], bf1[4][2];
    PROJ_LDFRAG(af0, bf0, 0, 0);

    const int NST = DD / 16;   // 16
    for (int s = 0; s < NST; s++) {
        const int cur = s & 1;
        PROJ_LDFRAG(af1, bf1, cur, 8);
        mma_sweep(acc, af0, bf0);
        __syncthreads();                       // all warps done reading stage cur
        if (s + 2 < NST) { PROJ_ISSUE(cur, (s + 2) * 16); CP_COMMIT(); }
        mma_sweep(acc, af1, bf1);
        if (s + 1 < NST) {
            if (s + 2 < NST) CP_WAIT1(); else CP_WAIT0();
            __syncthreads();
            PROJ_LDFRAG(af0, bf0, cur ^ 1, 0);
        }
    }
    #undef PROJ_ISSUE
    #undef PROJ_LDFRAG

    // epilogue
    #pragma unroll
    for (int mt = 0; mt < 4; mt++) {
        const int r0 = row0 + wm * 64 + mt * 16 + lr;
        #pragma unroll
        for (int nt = 0; nt < 4; nt++) {
            const int c = col0 + wn * 32 + nt * 8 + 2 * lc;
            const float b0 = bias[c], b1 = bias[c + 1];
            float v0 = acc[mt][nt][0] + b0;
            float v1 = acc[mt][nt][1] + b1;
            float v2 = acc[mt][nt][2] + b0;
            float v3 = acc[mt][nt][3] + b1;
            if (ACT) {
                v0 = (v0 > 0.0f) ? (v0 + 1.0f) : __expf(v0);
                v1 = (v1 > 0.0f) ? (v1 + 1.0f) : __expf(v1);
                v2 = (v2 > 0.0f) ? (v2 + 1.0f) : __expf(v2);
                v3 = (v3 > 0.0f) ? (v3 + 1.0f) : __expf(v3);
            }
            float2 p0 = { v0, v1 }, p1 = { v2, v3 };
            *(float2*)&Y[(size_t)r0 * DD + c]       = p0;
            *(float2*)&Y[(size_t)(r0 + 8) * DD + c] = p1;
        }
    }
}

// ============================================================
// kv split-K: kvpart[bz][d,h] = sum_{l in chunk} K[b,l,d]*V[b,l,h]
// Both operands [k(l)][feat] natural. grid = (2, 2, BB*KVS)
// ============================================================
__global__ __launch_bounds__(256)
void kv_mma()
{
    __shared__ __align__(16) float As[2][16*BP];   // [l][d]
    __shared__ __align__(16) float Bs[2][16*BP];   // [l][h]

    const int tid = threadIdx.x;
    const int h0 = blockIdx.x * 128;
    const int d0 = blockIdx.y * 128;
    const int bz = blockIdx.z;
    const int b  = bz / KVS;
    const int sp = bz % KVS;
    const int lchunk = LL / KVS;      // 512
    const size_t base = ((size_t)b * LL + (size_t)sp * lchunk) * DD;

    const int warp = tid >> 5, lane = tid & 31;
    const int wm = warp & 1, wn = warp >> 1;
    const int lr = lane >> 2, lc = lane & 3;

    const int k_r   = (2 * tid) >> 5;           // 0..15
    const int k_off = ((2 * tid) & 31) * 4;     // 0..124

    const float* Ag = g_K + base + (size_t)k_r * DD + d0 + k_off;
    const float* Bg = g_V + base + (size_t)k_r * DD + h0 + k_off;

    const uint32_t sA0 = (uint32_t)__cvta_generic_to_shared(&As[0][0]);
    const uint32_t sB0 = (uint32_t)__cvta_generic_to_shared(&Bs[0][0]);

    float acc[4][4][4] = {};

    #define KV_ISSUE(st, l0) do {                                              \
        cp16(sA0 + ((st)*16*BP + k_r*BP + k_off) * 4,     Ag + (size_t)(l0)*DD);      \
        cp16(sA0 + ((st)*16*BP + k_r*BP + k_off + 4) * 4, Ag + (size_t)(l0)*DD + 4);  \
        cp16(sB0 + ((st)*16*BP + k_r*BP + k_off) * 4,     Bg + (size_t)(l0)*DD);      \
        cp16(sB0 + ((st)*16*BP + k_r*BP + k_off + 4) * 4, Bg + (size_t)(l0)*DD + 4);  \
    } while (0)

    #define KV_LDFRAG(af, bf, st, kb) do {                                     \
        _Pragma("unroll")                                                      \
        for (int mt = 0; mt < 4; mt++) {                                       \
            const int m = wm * 64 + mt * 16 + lr;                              \
            af[mt][0] = f2tf(As[st][((kb) + lc)     * BP + m]);                \
            af[mt][1] = f2tf(As[st][((kb) + lc)     * BP + m + 8]);            \
            af[mt][2] = f2tf(As[st][((kb) + 4 + lc) * BP + m]);                \
            af[mt][3] = f2tf(As[st][((kb) + 4 + lc) * BP + m + 8]);            \
        }                                                                      \
        _Pragma("unroll")                                                      \
        for (int nt = 0; nt < 4; nt++) {                                       \
            const int n = wn * 32 + nt * 8 + lr;                               \
            bf[nt][0] = f2tf(Bs[st][((kb) + lc)     * BP + n]);                \
            bf[nt][1] = f2tf(Bs[st][((kb) + 4 + lc) * BP + n]);                \
        }                                                                      \
    } while (0)

    KV_ISSUE(0, 0);  CP_COMMIT();
    KV_ISSUE(1, 16); CP_COMMIT();
    CP_WAIT1();
    __syncthreads();

    uint32_t af0[4][4], bf0[4][2], af1[4][4], bf1[4][2];
    KV_LDFRAG(af0, bf0, 0, 0);

    const int NST = lchunk / 16;   // 32
    for (int s = 0; s < NST; s++) {
        const int cur = s & 1;
        KV_LDFRAG(af1, bf1, cur, 8);
        mma_sweep(acc, af0, bf0);
        __syncthreads();
        if (s + 2 < NST) { KV_ISSUE(cur, (s + 2) * 16); CP_COMMIT(); }
        mma_sweep(acc, af1, bf1);
        if (s + 1 < NST) {
            if (s + 2 < NST) CP_WAIT1(); else CP_WAIT0();
            __syncthreads();
            KV_LDFRAG(af0, bf0, cur ^ 1, 0);
        }
    }
    #undef KV_ISSUE
    #undef KV_LDFRAG

    float* outp = g_kvpart + (size_t)bz * DD * DD;
    #pragma unroll
    for (int mt = 0; mt < 4; mt++) {
        const int d = d0 + wm * 64 + mt * 16 + lr;
        #pragma unroll
        for (int nt = 0; nt < 4; nt++) {
            const int h = h0 + wn * 32 + nt * 8 + 2 * lc;
            float2 p0 = { acc[mt][nt][0], acc[mt][nt][1] };
            float2 p1 = { acc[mt][nt][2], acc[mt][nt][3] };
            *(float2*)&outp[(size_t)d * DD + h]       = p0;
            *(float2*)&outp[(size_t)(d + 8) * DD + h] = p1;
        }
    }
}

__global__ void reduce_kv_kernel()
{
    int i = blockIdx.x * blockDim.x + threadIdx.x;
    if (i >= BB * DD * DD) return;
    int b  = i / (DD * DD);
    int dh = i % (DD * DD);
    float s = 0.0f;
    #pragma unroll
    for (int sp = 0; sp < KVS; sp++)
        s += g_kvpart[(size_t)(b * KVS + sp) * DD * DD + dh];
    g_kv[i] = s;
}

__global__ void ksum_partial_kernel()
{
    int s = blockIdx.x, b = blockIdx.y, d = threadIdx.x;
    const int lchunk = LL / KS_SPLIT;
    const float* Kb = g_K + ((size_t)b * LL + (size_t)s * lchunk) * DD;
    float acc = 0.0f;
    for (int l = 0; l < lchunk; l++) acc += Kb[(size_t)l * DD + d];
    g_ksum_part[((size_t)s * BB + b) * DD + d] = acc;
}

__global__ void reduce_ksum_kernel()
{
    int i = blockIdx.x * blockDim.x + threadIdx.x;
    if (i >= BB * DD) return;
    int b = i / DD, d = i % DD;
    float acc = 0.0f;
    #pragma unroll
    for (int s = 0; s < KS_SPLIT; s++)
        acc += g_ksum_part[((size_t)s * BB + b) * DD + d];
    g_ksum[i] = acc;
}

__global__ void z_kernel()
{
    int gwarp = (blockIdx.x * blockDim.x + threadIdx.x) >> 5;
    int lane  = threadIdx.x & 31;
    if (gwarp >= ML) return;
    int b = gwarp / LL;
    const float4* qr = (const float4*)(g_Q + (size_t)gwarp * DD);
    const float4* ks = (const float4*)(g_ksum + (size_t)b * DD);
    float acc = 0.0f;
    #pragma unroll
    for (int c = lane; c < DD / 4; c += 32) {
        float4 qv = qr[c], kv4 = ks[c];
        acc = fmaf(qv.x, kv4.x, acc);
        acc = fmaf(qv.y, kv4.y, acc);
        acc = fmaf(qv.z, kv4.z, acc);
        acc = fmaf(qv.w, kv4.w, acc);
    }
    #pragma unroll
    for (int off = 16; off > 0; off >>= 1)
        acc += __shfl_xor_sync(0xffffffffu, acc, off);
    if (lane == 0) g_z[gwarp] = acc + 1e-6f;
}

// ============================================================
// out[row,:] = (Q[row,:] @ kv[b]) / z[row]
// ============================================================
__global__ __launch_bounds__(256)
void out_mma(float* __restrict__ out)
{
    __shared__ __align__(16) float As[2][128*AP];
    __shared__ __align__(16) float Bs[2][16*BP];

    const int tid  = threadIdx.x;
    const int row0 = blockIdx.y * 128;
    const int col0 = blockIdx.x * 128;
    const int b    = row0 / LL;

    const int warp = tid >> 5, lane = tid & 31;
    const int wm = warp & 1, wn = warp >> 1;
    const int lr = lane >> 2, lc = lane & 3;

    const int a_r   = (2 * tid) >> 2;
    const int a_off = ((2 * tid) & 3) * 4;
    const int b_r   = (2 * tid) >> 5;
    const int b_off = ((2 * tid) & 31) * 4;

    const float* Ag = g_Q + (size_t)(row0 + a_r) * DD + a_off;
    const float* Bg = g_kv + (size_t)b * DD * DD + (size_t)b_r * DD + col0 + b_off;

    const uint32_t sA0 = (uint32_t)__cvta_generic_to_shared(&As[0][0]);
    const uint32_t sB0 = (uint32_t)__cvta_generic_to_shared(&Bs[0][0]);

    float acc[4][4][4] = {};

    #define O_ISSUE(st, k0) do {                                               \
        cp16(sA0 + ((st)*128*AP + a_r*AP + a_off) * 4,      Ag + (k0));        \
        cp16(sA0 + ((st)*128*AP + a_r*AP + a_off + 4) * 4,  Ag + (k0) + 4);    \
        cp16(sB0 + ((st)*16*BP + b_r*BP + b_off) * 4,       Bg + (size_t)(k0)*DD);     \
        cp16(sB0 + ((st)*16*BP + b_r*BP + b_off + 4) * 4,   Bg + (size_t)(k0)*DD + 4); \
    } while (0)

    #define O_LDFRAG(af, bf, st, kb) do {                                      \
        _Pragma("unroll")                                                      \
        for (int mt = 0; mt < 4; mt++) {                                       \
            const int m = wm * 64 + mt * 16 + lr;                              \
            af[mt][0] = f2tf(As[st][(m)   * AP + (kb) + lc]);                  \
            af[mt][1] = f2tf(As[st][(m+8) * AP + (kb) + lc]);                  \
            af[mt][2] = f2tf(As[st][(m)   * AP + (kb) + lc + 4]);              \
            af[mt][3] = f2tf(As[st][(m+8) * AP + (kb) + lc + 4]);              \
        }                                                                      \
        _Pragma("unroll")                                                      \
        for (int nt = 0; nt < 4; nt++) {                                       \
            const int n = wn * 32 + nt * 8 + lr;                               \
            bf[nt][0] = f2tf(Bs[st][((kb) + lc)     * BP + n]);                \
            bf[nt][1] = f2tf(Bs[st][((kb) + 4 + lc) * BP + n]);                \
        }                                                                      \
    } while (0)

    O_ISSUE(0, 0);  CP_COMMIT();
    O_ISSUE(1, 16); CP_COMMIT();
    CP_WAIT1();
    __syncthreads();

    uint32_t af0[4][4], bf0[4][2], af1[4][4], bf1[4][2];
    O_LDFRAG(af0, bf0, 0, 0);

    const int NST = DD / 16;
    for (int s = 0; s < NST; s++) {
        const int cur = s & 1;
        O_LDFRAG(af1, bf1, cur, 8);
        mma_sweep(acc, af0, bf0);
        __syncthreads();
        if (s + 2 < NST) { O_ISSUE(cur, (s + 2) * 16); CP_COMMIT(); }
        mma_sweep(acc, af1, bf1);
        if (s + 1 < NST) {
            if (s + 2 < NST) CP_WAIT1(); else CP_WAIT0();
            __syncthreads();
            O_LDFRAG(af0, bf0, cur ^ 1, 0);
        }
    }
    #undef O_ISSUE
    #undef O_LDFRAG

    #pragma unroll
    for (int mt = 0; mt < 4; mt++) {
        const int r0 = row0 + wm * 64 + mt * 16 + lr;
        const float iz0 = 1.0f / g_z[r0];
        const float iz1 = 1.0f / g_z[r0 + 8];
        #pragma unroll
        for (int nt = 0; nt < 4; nt++) {
            const int c = col0 + wn * 32 + nt * 8 + 2 * lc;
            float2 p0 = { acc[mt][nt][0] * iz0, acc[mt][nt][1] * iz0 };
            float2 p1 = { acc[mt][nt][2] * iz1, acc[mt][nt][3] * iz1 };
            *(float2*)&out[(size_t)r0 * DD + c]       = p0;
            *(float2*)&out[(size_t)(r0 + 8) * DD + c] = p1;
        }
    }
}

// ============================================================
extern "C" void kernel_launch(void* const* d_in, const int* in_sizes, int n_in,
                              void* d_out, int out_size)
{
    const float* q  = (const float*)d_in[0];
    const float* k  = (const float*)d_in[1];
    const float* v  = (const float*)d_in[2];
    const float* Wq = (const float*)d_in[3];
    const float* bq = (const float*)d_in[4];
    const float* Wk = (const float*)d_in[5];
    const float* bk = (const float*)d_in[6];
    const float* Wv = (const float*)d_in[7];
    const float* bv = (const float*)d_in[8];
    float* out = (float*)d_out;

    float *dQ, *dK, *dV;
    cudaGetSymbolAddress((void**)&dQ, g_Q);
    cudaGetSymbolAddress((void**)&dK, g_K);
    cudaGetSymbolAddress((void**)&dV, g_V);

    dim3 gProj(DD / 128, ML / 128);
    proj_mma<1><<<gProj, 256>>>(q, Wq, bq, dQ);
    proj_mma<1><<<gProj, 256>>>(k, Wk, bk, dK);
    proj_mma<0><<<gProj, 256>>>(v, Wv, bv, dV);

    dim3 gKV(DD / 128, DD / 128, BB * KVS);
    kv_mma<<<gKV, 256>>>();
    reduce_kv_kernel<<<(BB * DD * DD + 255) / 256, 256>>>();

    dim3 gKS(KS_SPLIT, BB);
    ksum_partial_kernel<<<gKS, 256>>>();
    reduce_ksum_kernel<<<(BB * DD + 255) / 256, 256>>>();

    z_kernel<<<(ML * 32 + 255) / 256, 256>>>();

    dim3 gOut(DD / 128, ML / 128);
    out_mma<<<gOut, 256>>>(out);
}

// round 5
// speedup vs baseline: 3.4861x; 1.0616x over previous
#include <cuda_runtime.h>
#include <math.h>
#include <stdint.h>

#define BB 8
#define LL 4096
#define DD 256
#define ML (BB*LL)          // 32768 rows
#define KVS 8               // split-K for kv (deterministic)

#define AP 20    // proj/out A smem row stride (16 k + 4 pad floats)
#define BP 132   // [k][n] smem row stride

// ---- scratch (device globals; no allocations allowed) ----
__device__ float g_Q[ML*DD];     // tf32-pre-rounded
__device__ float g_K[ML*DD];     // tf32-pre-rounded
__device__ float g_V[ML*DD];     // tf32-pre-rounded
__device__ float g_kvpart[KVS*BB*DD*DD];
__device__ float g_kv[BB*DD*DD];
__device__ float g_kcs[256*DD];  // K colsum partials per 128-row block
__device__ float g_ksum[BB*DD];
__device__ float g_zpart[2*ML];  // z partials per 128-col block

// ---- helpers ----
__device__ __forceinline__ uint32_t f2tf(float x) {
    uint32_t r; asm("cvt.rna.tf32.f32 %0, %1;" : "=r"(r) : "f"(x)); return r;
}
__device__ __forceinline__ void mma8(float* d, const uint32_t* a, const uint32_t* b) {
    asm volatile(
        "mma.sync.aligned.m16n8k8.row.col.f32.tf32.tf32.f32 "
        "{%0,%1,%2,%3}, {%4,%5,%6,%7}, {%8,%9}, {%0,%1,%2,%3};\n"
        : "+f"(d[0]), "+f"(d[1]), "+f"(d[2]), "+f"(d[3])
        : "r"(a[0]), "r"(a[1]), "r"(a[2]), "r"(a[3]), "r"(b[0]), "r"(b[1]));
}
__device__ __forceinline__ void cp16(uint32_t saddr, const void* g) {
    asm volatile("cp.async.cg.shared.global [%0], [%1], 16;\n"
                 :: "r"(saddr), "l"(g) : "memory");
}
#define CP_COMMIT() asm volatile("cp.async.commit_group;\n" ::: "memory")
#define CP_WAIT1()  asm volatile("cp.async.wait_group 1;\n" ::: "memory")
#define CP_WAIT0()  asm volatile("cp.async.wait_group 0;\n" ::: "memory")

__device__ __forceinline__ void mma_sweep(float acc[4][4][4],
                                          const uint32_t af[4][4],
                                          const uint32_t bf[4][2]) {
    #pragma unroll
    for (int mt = 0; mt < 4; mt++)
        #pragma unroll
        for (int nt = 0; nt < 4; nt++)
            mma8(acc[mt][nt], af[mt], bf[nt]);
}

// ============================================================
// Projection: Y = act(X @ W + bias), written tf32-pre-rounded.
// MODE 0: plain (V). MODE 1: +column-sum partials (K).
// MODE 2: +z row partials vs g_ksum (Q).
// ============================================================
template<int ACT, int MODE>
__global__ __launch_bounds__(256)
void proj_mma(const float* __restrict__ X, const float* __restrict__ W,
              const float* __restrict__ bias, float* __restrict__ Y)
{
    __shared__ __align__(16) float As[2][128*AP];   // [m][k]
    __shared__ __align__(16) float Bs[2][16*BP];    // [k][n]
    __shared__ float red_s[4][128];                 // fused-reduction staging

    const int tid  = threadIdx.x;
    const int row0 = blockIdx.y * 128;
    const int col0 = blockIdx.x * 128;

    const int warp = tid >> 5, lane = tid & 31;
    const int wm = warp & 1, wn = warp >> 1;
    const int lr = lane >> 2, lc = lane & 3;

    const int a_r   = (2 * tid) >> 2;
    const int a_off = ((2 * tid) & 3) * 4;
    const int b_r   = (2 * tid) >> 5;
    const int b_off = ((2 * tid) & 31) * 4;

    const float* Ag = X + (size_t)(row0 + a_r) * DD + a_off;
    const float* Bg = W + (size_t)b_r * DD + col0 + b_off;

    const uint32_t sA0 = (uint32_t)__cvta_generic_to_shared(&As[0][0]);
    const uint32_t sB0 = (uint32_t)__cvta_generic_to_shared(&Bs[0][0]);

    float acc[4][4][4] = {};

    #define PROJ_ISSUE(st, k0) do {                                           \
        cp16(sA0 + ((st)*128*AP + a_r*AP + a_off) * 4,      Ag + (k0));        \
        cp16(sA0 + ((st)*128*AP + a_r*AP + a_off + 4) * 4,  Ag + (k0) + 4);    \
        cp16(sB0 + ((st)*16*BP + b_r*BP + b_off) * 4,       Bg + (size_t)(k0)*DD);     \
        cp16(sB0 + ((st)*16*BP + b_r*BP + b_off + 4) * 4,   Bg + (size_t)(k0)*DD + 4); \
    } while (0)

    #define PROJ_LDFRAG(af, bf, st, kb) do {                                   \
        _Pragma("unroll")                                                      \
        for (int mt = 0; mt < 4; mt++) {                                       \
            const int m = wm * 64 + mt * 16 + lr;                              \
            af[mt][0] = f2tf(As[st][(m)   * AP + (kb) + lc]);                  \
            af[mt][1] = f2tf(As[st][(m+8) * AP + (kb) + lc]);                  \
            af[mt][2] = f2tf(As[st][(m)   * AP + (kb) + lc + 4]);              \
            af[mt][3] = f2tf(As[st][(m+8) * AP + (kb) + lc + 4]);              \
        }                                                                      \
        _Pragma("unroll")                                                      \
        for (int nt = 0; nt < 4; nt++) {                                       \
            const int n = wn * 32 + nt * 8 + lr;                               \
            bf[nt][0] = f2tf(Bs[st][((kb) + lc)     * BP + n]);                \
            bf[nt][1] = f2tf(Bs[st][((kb) + 4 + lc) * BP + n]);                \
        }                                                                      \
    } while (0)

    PROJ_ISSUE(0, 0);  CP_COMMIT();
    PROJ_ISSUE(1, 16); CP_COMMIT();
    CP_WAIT1();
    __syncthreads();

    uint32_t af0[4][4], bf0[4][2], af1[4][4], bf1[4][2];
    PROJ_LDFRAG(af0, bf0, 0, 0);

    const int NST = DD / 16;   // 16
    for (int s = 0; s < NST; s++) {
        const int cur = s & 1;
        PROJ_LDFRAG(af1, bf1, cur, 8);
        mma_sweep(acc, af0, bf0);
        __syncthreads();
        if (s + 2 < NST) { PROJ_ISSUE(cur, (s + 2) * 16); CP_COMMIT(); }
        mma_sweep(acc, af1, bf1);
        if (s + 1 < NST) {
            if (s + 2 < NST) CP_WAIT1(); else CP_WAIT0();
            __syncthreads();
            PROJ_LDFRAG(af0, bf0, cur ^ 1, 0);
        }
    }
    #undef PROJ_ISSUE
    #undef PROJ_LDFRAG

    // ---- epilogue (activation, fused reductions, tf32-rounded store) ----
    float cs[4][2];    // MODE1: [nt][c01] column-sum partials
    float za[4][2];    // MODE2: [mt][rhalf] z row partials
    float ksv[4][2];   // MODE2: ksum values for this thread's columns
    if (MODE == 1) {
        #pragma unroll
        for (int nt = 0; nt < 4; nt++) { cs[nt][0] = 0.f; cs[nt][1] = 0.f; }
    }
    if (MODE == 2) {
        const int b = row0 >> 12;   // 4096 rows per batch
        #pragma unroll
        for (int mt = 0; mt < 4; mt++) { za[mt][0] = 0.f; za[mt][1] = 0.f; }
        #pragma unroll
        for (int nt = 0; nt < 4; nt++) {
            const int c = col0 + wn * 32 + nt * 8 + 2 * lc;
            ksv[nt][0] = g_ksum[b * DD + c];
            ksv[nt][1] = g_ksum[b * DD + c + 1];
        }
    }

    #pragma unroll
    for (int mt = 0; mt < 4; mt++) {
        const int r0 = row0 + wm * 64 + mt * 16 + lr;
        #pragma unroll
        for (int nt = 0; nt < 4; nt++) {
            const int c = col0 + wn * 32 + nt * 8 + 2 * lc;
            const float b0 = bias[c], b1 = bias[c + 1];
            float v0 = acc[mt][nt][0] + b0;
            float v1 = acc[mt][nt][1] + b1;
            float v2 = acc[mt][nt][2] + b0;
            float v3 = acc[mt][nt][3] + b1;
            if (ACT) {
                v0 = (v0 > 0.0f) ? (v0 + 1.0f) : __expf(v0);
                v1 = (v1 > 0.0f) ? (v1 + 1.0f) : __expf(v1);
                v2 = (v2 > 0.0f) ? (v2 + 1.0f) : __expf(v2);
                v3 = (v3 > 0.0f) ? (v3 + 1.0f) : __expf(v3);
            }
            if (MODE == 1) {
                cs[nt][0] += v0 + v2;
                cs[nt][1] += v1 + v3;
            }
            if (MODE == 2) {
                za[mt][0] = fmaf(v0, ksv[nt][0], fmaf(v1, ksv[nt][1], za[mt][0]));
                za[mt][1] = fmaf(v2, ksv[nt][0], fmaf(v3, ksv[nt][1], za[mt][1]));
            }
            float2 p0 = { __uint_as_float(f2tf(v0)), __uint_as_float(f2tf(v1)) };
            float2 p1 = { __uint_as_float(f2tf(v2)), __uint_as_float(f2tf(v3)) };
            *(float2*)&Y[(size_t)r0 * DD + c]       = p0;
            *(float2*)&Y[(size_t)(r0 + 8) * DD + c] = p1;
        }
    }

    if (MODE == 1) {
        // reduce over lr (lane bits 2..4); every lane ends with the warp total
        #pragma unroll
        for (int nt = 0; nt < 4; nt++) {
            #pragma unroll
            for (int off = 4; off < 32; off <<= 1) {
                cs[nt][0] += __shfl_xor_sync(0xffffffffu, cs[nt][0], off);
                cs[nt][1] += __shfl_xor_sync(0xffffffffu, cs[nt][1], off);
            }
        }
        if (lr == 0) {
            #pragma unroll
            for (int nt = 0; nt < 4; nt++) {
                const int cl = wn * 32 + nt * 8 + 2 * lc;
                red_s[wm][cl]     = cs[nt][0];
                red_s[wm][cl + 1] = cs[nt][1];
            }
        }
        __syncthreads();
        if (tid < 128)
            g_kcs[(size_t)blockIdx.y * DD + col0 + tid] = red_s[0][tid] + red_s[1][tid];
    }
    if (MODE == 2) {
        // reduce over lc (lane bits 0..1)
        #pragma unroll
        for (int mt = 0; mt < 4; mt++) {
            #pragma unroll
            for (int off = 1; off < 4; off <<= 1) {
                za[mt][0] += __shfl_xor_sync(0xffffffffu, za[mt][0], off);
                za[mt][1] += __shfl_xor_sync(0xffffffffu, za[mt][1], off);
            }
        }
        if (lc == 0) {
            #pragma unroll
            for (int mt = 0; mt < 4; mt++) {
                const int rl = wm * 64 + mt * 16 + lr;
                red_s[wn][rl]     = za[mt][0];
                red_s[wn][rl + 8] = za[mt][1];
            }
        }
        __syncthreads();
        if (tid < 128)
            g_zpart[(size_t)blockIdx.x * ML + row0 + tid] =
                red_s[0][tid] + red_s[1][tid] + red_s[2][tid] + red_s[3][tid];
    }
}

// ksum[b,d] = sum over 32 row-blocks of g_kcs
__global__ void reduce_kcs_kernel()
{
    int i = blockIdx.x * blockDim.x + threadIdx.x;
    if (i >= BB * DD) return;
    int b = i / DD, d = i % DD;
    float s = 0.0f;
    #pragma unroll
    for (int j = 0; j < 32; j++)
        s += g_kcs[(size_t)(b * 32 + j) * DD + d];
    g_ksum[i] = s;
}

// ============================================================
// kv split-K: pre-rounded inputs -> no cvt in the hot loop.
// ============================================================
__global__ __launch_bounds__(256)
void kv_mma()
{
    __shared__ __align__(16) float As[2][16*BP];   // [l][d]
    __shared__ __align__(16) float Bs[2][16*BP];   // [l][h]

    const int tid = threadIdx.x;
    const int h0 = blockIdx.x * 128;
    const int d0 = blockIdx.y * 128;
    const int bz = blockIdx.z;
    const int b  = bz / KVS;
    const int sp = bz % KVS;
    const int lchunk = LL / KVS;      // 512
    const size_t base = ((size_t)b * LL + (size_t)sp * lchunk) * DD;

    const int warp = tid >> 5, lane = tid & 31;
    const int wm = warp & 1, wn = warp >> 1;
    const int lr = lane >> 2, lc = lane & 3;

    const int k_r   = (2 * tid) >> 5;
    const int k_off = ((2 * tid) & 31) * 4;

    const float* Ag = g_K + base + (size_t)k_r * DD + d0 + k_off;
    const float* Bg = g_V + base + (size_t)k_r * DD + h0 + k_off;

    const uint32_t sA0 = (uint32_t)__cvta_generic_to_shared(&As[0][0]);
    const uint32_t sB0 = (uint32_t)__cvta_generic_to_shared(&Bs[0][0]);

    float acc[4][4][4] = {};

    #define KV_ISSUE(st, l0) do {                                              \
        cp16(sA0 + ((st)*16*BP + k_r*BP + k_off) * 4,     Ag + (size_t)(l0)*DD);      \
        cp16(sA0 + ((st)*16*BP + k_r*BP + k_off + 4) * 4, Ag + (size_t)(l0)*DD + 4);  \
        cp16(sB0 + ((st)*16*BP + k_r*BP + k_off) * 4,     Bg + (size_t)(l0)*DD);      \
        cp16(sB0 + ((st)*16*BP + k_r*BP + k_off + 4) * 4, Bg + (size_t)(l0)*DD + 4);  \
    } while (0)

    #define KV_LDFRAG(af, bf, st, kb) do {                                     \
        _Pragma("unroll")                                                      \
        for (int mt = 0; mt < 4; mt++) {                                       \
            const int m = wm * 64 + mt * 16 + lr;                              \
            af[mt][0] = __float_as_uint(As[st][((kb) + lc)     * BP + m]);     \
            af[mt][1] = __float_as_uint(As[st][((kb) + lc)     * BP + m + 8]); \
            af[mt][2] = __float_as_uint(As[st][((kb) + 4 + lc) * BP + m]);     \
            af[mt][3] = __float_as_uint(As[st][((kb) + 4 + lc) * BP + m + 8]); \
        }                                                                      \
        _Pragma("unroll")                                                      \
        for (int nt = 0; nt < 4; nt++) {                                       \
            const int n = wn * 32 + nt * 8 + lr;                               \
            bf[nt][0] = __float_as_uint(Bs[st][((kb) + lc)     * BP + n]);     \
            bf[nt][1] = __float_as_uint(Bs[st][((kb) + 4 + lc) * BP + n]);     \
        }                                                                      \
    } while (0)

    KV_ISSUE(0, 0);  CP_COMMIT();
    KV_ISSUE(1, 16); CP_COMMIT();
    CP_WAIT1();
    __syncthreads();

    uint32_t af0[4][4], bf0[4][2], af1[4][4], bf1[4][2];
    KV_LDFRAG(af0, bf0, 0, 0);

    const int NST = lchunk / 16;   // 32
    for (int s = 0; s < NST; s++) {
        const int cur = s & 1;
        KV_LDFRAG(af1, bf1, cur, 8);
        mma_sweep(acc, af0, bf0);
        __syncthreads();
        if (s + 2 < NST) { KV_ISSUE(cur, (s + 2) * 16); CP_COMMIT(); }
        mma_sweep(acc, af1, bf1);
        if (s + 1 < NST) {
            if (s + 2 < NST) CP_WAIT1(); else CP_WAIT0();
            __syncthreads();
            KV_LDFRAG(af0, bf0, cur ^ 1, 0);
        }
    }
    #undef KV_ISSUE
    #undef KV_LDFRAG

    float* outp = g_kvpart + (size_t)bz * DD * DD;
    #pragma unroll
    for (int mt = 0; mt < 4; mt++) {
        const int d = d0 + wm * 64 + mt * 16 + lr;
        #pragma unroll
        for (int nt = 0; nt < 4; nt++) {
            const int h = h0 + wn * 32 + nt * 8 + 2 * lc;
            float2 p0 = { acc[mt][nt][0], acc[mt][nt][1] };
            float2 p1 = { acc[mt][nt][2], acc[mt][nt][3] };
            *(float2*)&outp[(size_t)d * DD + h]       = p0;
            *(float2*)&outp[(size_t)(d + 8) * DD + h] = p1;
        }
    }
}

__global__ void reduce_kv_kernel()
{
    int i = blockIdx.x * blockDim.x + threadIdx.x;
    if (i >= BB * DD * DD) return;
    int b  = i / (DD * DD);
    int dh = i % (DD * DD);
    float s = 0.0f;
    #pragma unroll
    for (int sp = 0; sp < KVS; sp++)
        s += g_kvpart[(size_t)(b * KVS + sp) * DD * DD + dh];
    // pre-round for the out GEMM (tf32 consumed there)
    g_kv[i] = __uint_as_float(f2tf(s));
}

// ============================================================
// out[row,:] = (Q[row,:] @ kv[b]) / z[row]; z from fused partials.
// ============================================================
__global__ __launch_bounds__(256)
void out_mma(float* __restrict__ out)
{
    __shared__ __align__(16) float As[2][128*AP];
    __shared__ __align__(16) float Bs[2][16*BP];

    const int tid  = threadIdx.x;
    const int row0 = blockIdx.y * 128;
    const int col0 = blockIdx.x * 128;
    const int b    = row0 / LL;

    const int warp = tid >> 5, lane = tid & 31;
    const int wm = warp & 1, wn = warp >> 1;
    const int lr = lane >> 2, lc = lane & 3;

    const int a_r   = (2 * tid) >> 2;
    const int a_off = ((2 * tid) & 3) * 4;
    const int b_r   = (2 * tid) >> 5;
    const int b_off = ((2 * tid) & 31) * 4;

    const float* Ag = g_Q + (size_t)(row0 + a_r) * DD + a_off;
    const float* Bg = g_kv + (size_t)b * DD * DD + (size_t)b_r * DD + col0 + b_off;

    const uint32_t sA0 = (uint32_t)__cvta_generic_to_shared(&As[0][0]);
    const uint32_t sB0 = (uint32_t)__cvta_generic_to_shared(&Bs[0][0]);

    float acc[4][4][4] = {};

    #define O_ISSUE(st, k0) do {                                               \
        cp16(sA0 + ((st)*128*AP + a_r*AP + a_off) * 4,      Ag + (k0));        \
        cp16(sA0 + ((st)*128*AP + a_r*AP + a_off + 4) * 4,  Ag + (k0) + 4);    \
        cp16(sB0 + ((st)*16*BP + b_r*BP + b_off) * 4,       Bg + (size_t)(k0)*DD);     \
        cp16(sB0 + ((st)*16*BP + b_r*BP + b_off + 4) * 4,   Bg + (size_t)(k0)*DD + 4); \
    } while (0)

    #define O_LDFRAG(af, bf, st, kb) do {                                      \
        _Pragma("unroll")                                                      \
        for (int mt = 0; mt < 4; mt++) {                                       \
            const int m = wm * 64 + mt * 16 + lr;                              \
            af[mt][0] = __float_as_uint(As[st][(m)   * AP + (kb) + lc]);       \
            af[mt][1] = __float_as_uint(As[st][(m+8) * AP + (kb) + lc]);       \
            af[mt][2] = __float_as_uint(As[st][(m)   * AP + (kb) + lc + 4]);   \
            af[mt][3] = __float_as_uint(As[st][(m+8) * AP + (kb) + lc + 4]);   \
        }                                                                      \
        _Pragma("unroll")                                                      \
        for (int nt = 0; nt < 4; nt++) {                                       \
            const int n = wn * 32 + nt * 8 + lr;                               \
            bf[nt][0] = __float_as_uint(Bs[st][((kb) + lc)     * BP + n]);     \
            bf[nt][1] = __float_as_uint(Bs[st][((kb) + 4 + lc) * BP + n]);     \
        }                                                                      \
    } while (0)

    O_ISSUE(0, 0);  CP_COMMIT();
    O_ISSUE(1, 16); CP_COMMIT();
    CP_WAIT1();
    __syncthreads();

    uint32_t af0[4][4], bf0[4][2], af1[4][4], bf1[4][2];
    O_LDFRAG(af0, bf0, 0, 0);

    const int NST = DD / 16;
    for (int s = 0; s < NST; s++) {
        const int cur = s & 1;
        O_LDFRAG(af1, bf1, cur, 8);
        mma_sweep(acc, af0, bf0);
        __syncthreads();
        if (s + 2 < NST) { O_ISSUE(cur, (s + 2) * 16); CP_COMMIT(); }
        mma_sweep(acc, af1, bf1);
        if (s + 1 < NST) {
            if (s + 2 < NST) CP_WAIT1(); else CP_WAIT0();
            __syncthreads();
            O_LDFRAG(af0, bf0, cur ^ 1, 0);
        }
    }
    #undef O_ISSUE
    #undef O_LDFRAG

    #pragma unroll
    for (int mt = 0; mt < 4; mt++) {
        const int r0 = row0 + wm * 64 + mt * 16 + lr;
        const float iz0 = 1.0f / (g_zpart[r0]     + g_zpart[ML + r0]     + 1e-6f);
        const float iz1 = 1.0f / (g_zpart[r0 + 8] + g_zpart[ML + r0 + 8] + 1e-6f);
        #pragma unroll
        for (int nt = 0; nt < 4; nt++) {
            const int c = col0 + wn * 32 + nt * 8 + 2 * lc;
            float2 p0 = { acc[mt][nt][0] * iz0, acc[mt][nt][1] * iz0 };
            float2 p1 = { acc[mt][nt][2] * iz1, acc[mt][nt][3] * iz1 };
            *(float2*)&out[(size_t)r0 * DD + c]       = p0;
            *(float2*)&out[(size_t)(r0 + 8) * DD + c] = p1;
        }
    }
}

// ============================================================
extern "C" void kernel_launch(void* const* d_in, const int* in_sizes, int n_in,
                              void* d_out, int out_size)
{
    const float* q  = (const float*)d_in[0];
    const float* k  = (const float*)d_in[1];
    const float* v  = (const float*)d_in[2];
    const float* Wq = (const float*)d_in[3];
    const float* bq = (const float*)d_in[4];
    const float* Wk = (const float*)d_in[5];
    const float* bk = (const float*)d_in[6];
    const float* Wv = (const float*)d_in[7];
    const float* bv = (const float*)d_in[8];
    float* out = (float*)d_out;

    float *dQ, *dK, *dV;
    cudaGetSymbolAddress((void**)&dQ, g_Q);
    cudaGetSymbolAddress((void**)&dK, g_K);
    cudaGetSymbolAddress((void**)&dV, g_V);

    dim3 gProj(DD / 128, ML / 128);

    // V (plain), K (+colsum partials)
    proj_mma<0,0><<<gProj, 256>>>(v, Wv, bv, dV);
    proj_mma<1,1><<<gProj, 256>>>(k, Wk, bk, dK);

    // ksum from K colsum partials
    reduce_kcs_kernel<<<(BB * DD + 255) / 256, 256>>>();

    // Q (+z partials, needs g_ksum)
    proj_mma<1,2><<<gProj, 256>>>(q, Wq, bq, dQ);

    // kv = K^T V (split-K + deterministic reduce, pre-rounded output)
    dim3 gKV(DD / 128, DD / 128, BB * KVS);
    kv_mma<<<gKV, 256>>>();
    reduce_kv_kernel<<<(BB * DD * DD + 255) / 256, 256>>>();

    // out = (Q @ kv) / z
    dim3 gOut(DD / 128, ML / 128);
    out_mma<<<gOut, 256>>>(out);
}